// round 13
// baseline (speedup 1.0000x reference)
#include <cuda_runtime.h>
#include <cuda_bf16.h>
#include <cstddef>

// ---------------------------------------------------------------------------
// BiGRU: B=32, S=512, I=512, H=512, L=2, bidirectional.
//   gx  = x @ wx^T + bx  (tf32 tensor-core GEMM, double-buffered smem)
//   recurrence: persistent kernel, f32x2 FFMA, per-jtile release flags.
//   This round: warp-asymmetric step tail — warps 8-15 skip fold/epilogue
//   and run ahead into step t+1's FMA while warps 0-7 finish the tail and
//   release via a 256-thread named barrier. red[] parity double-buffered.
// ---------------------------------------------------------------------------

#define BATCH 32
#define SEQ   512
#define HID   512
#define G3H   1536
#define MROWS (SEQ * BATCH)   // 16384

typedef unsigned long long ull;

__device__ float g_gx[(size_t)2 * MROWS * G3H];
__device__ float g_y0[(size_t)BATCH * SEQ * 2 * HID];
__device__ float g_h[(size_t)2 * HID * BATCH];      // [dir][k][b]
__device__ unsigned g_flag[2][16][32];              // [dir][group][slot]

__device__ __forceinline__ unsigned ld_acquire(const unsigned* p) {
    unsigned v;
    asm volatile("ld.acquire.gpu.u32 %0, [%1];" : "=r"(v) : "l"(p) : "memory");
    return v;
}
__device__ __forceinline__ void st_release(unsigned* p, unsigned v) {
    asm volatile("st.release.gpu.u32 [%0], %1;" :: "l"(p), "r"(v) : "memory");
}
__device__ __forceinline__ float ldcg(const float* p) {
    float v;
    asm volatile("ld.global.cg.f32 %0, [%1];" : "=f"(v) : "l"(p));
    return v;
}
__device__ __forceinline__ unsigned f2tf32(float x) {
    unsigned u;
    asm("cvt.rna.tf32.f32 %0, %1;" : "=r"(u) : "f"(x));
    return u;
}
__device__ __forceinline__ void fma2(ull& acc, ull a, ull b) {
    asm("fma.rn.f32x2 %0, %1, %2, %0;" : "+l"(acc) : "l"(a), "l"(b));
}
__device__ __forceinline__ ull add2(ull a, ull b) {
    ull d;
    asm("add.rn.f32x2 %0, %1, %2;" : "=l"(d) : "l"(a), "l"(b));
    return d;
}
__device__ __forceinline__ ull dup2(float x) {
    ull d;
    asm("mov.b64 %0, {%1, %1};" : "=l"(d) : "r"(__float_as_uint(x)));
    return d;
}
__device__ __forceinline__ ull pack2(float lo, float hi) {
    ull d;
    asm("mov.b64 %0, {%1, %2};" : "=l"(d)
        : "r"(__float_as_uint(lo)), "r"(__float_as_uint(hi)));
    return d;
}
__device__ __forceinline__ float half2f(ull v, int hi) {
    unsigned lo, hh;
    asm("mov.b64 {%0, %1}, %2;" : "=r"(lo), "=r"(hh) : "l"(v));
    return __uint_as_float(hi ? hh : lo);
}
__device__ __forceinline__ float sigf(float x) {
    return 1.f / (1.f + __expf(-x));
}
__device__ __forceinline__ float tanh_fast(float x) {
    float e = __expf(2.f * x);
    return 1.f - 2.f / (e + 1.f);
}

// ---------------------------------------------------------------------------
// tf32 GEMM, 2-stage smem double buffer (unchanged, proven).
// ---------------------------------------------------------------------------
#define GPAD 20

__global__ void __launch_bounds__(256) gemm_gx(
    const float* __restrict__ X, int in_dim,
    const float* __restrict__ Wf, const float* __restrict__ bf,
    const float* __restrict__ Wb, const float* __restrict__ bb)
{
    __shared__ float As[2][128 * GPAD];
    __shared__ float Ws[2][128 * GPAD];

    const int dir = blockIdx.z;
    const float* W    = dir ? Wb : Wf;
    const float* bias = dir ? bb : bf;
    const int m0 = blockIdx.x * 128;
    const int n0 = blockIdx.y * 128;
    const int tid  = threadIdx.x;
    const int warp = tid >> 5;
    const int lane = tid & 31;
    const int wm = warp >> 2;
    const int wn = warp & 3;
    const int gid = lane >> 2;
    const int tg  = lane & 3;

    const int row0 = tid >> 2;
    const int kq   = (tid & 3) << 2;
    const int row1 = row0 + 64;

    const int mA0 = m0 + row0, mA1 = m0 + row1;
    const float* pA0 = X + ((size_t)(mA0 & 31) * SEQ + (size_t)(mA0 >> 5)) * in_dim + kq;
    const float* pA1 = X + ((size_t)(mA1 & 31) * SEQ + (size_t)(mA1 >> 5)) * in_dim + kq;
    const float* pW0 = W + (size_t)(n0 + row0) * in_dim + kq;
    const float* pW1 = W + (size_t)(n0 + row1) * in_dim + kq;

    const int nk = in_dim >> 4;

    float acc[16][4];
#pragma unroll
    for (int i = 0; i < 16; i++)
#pragma unroll
        for (int c = 0; c < 4; c++) acc[i][c] = 0.f;

    float4 ra0 = __ldg((const float4*)pA0);
    float4 ra1 = __ldg((const float4*)pA1);
    float4 rw0 = __ldg((const float4*)pW0);
    float4 rw1 = __ldg((const float4*)pW1);

    {
        unsigned* ap0 = (unsigned*)&As[0][row0 * GPAD + kq];
        ap0[0] = f2tf32(ra0.x); ap0[1] = f2tf32(ra0.y);
        ap0[2] = f2tf32(ra0.z); ap0[3] = f2tf32(ra0.w);
        unsigned* ap1 = (unsigned*)&As[0][row1 * GPAD + kq];
        ap1[0] = f2tf32(ra1.x); ap1[1] = f2tf32(ra1.y);
        ap1[2] = f2tf32(ra1.z); ap1[3] = f2tf32(ra1.w);
        unsigned* wp0 = (unsigned*)&Ws[0][row0 * GPAD + kq];
        wp0[0] = f2tf32(rw0.x); wp0[1] = f2tf32(rw0.y);
        wp0[2] = f2tf32(rw0.z); wp0[3] = f2tf32(rw0.w);
        unsigned* wp1 = (unsigned*)&Ws[0][row1 * GPAD + kq];
        wp1[0] = f2tf32(rw1.x); wp1[1] = f2tf32(rw1.y);
        wp1[2] = f2tf32(rw1.z); wp1[3] = f2tf32(rw1.w);
    }
    __syncthreads();

    for (int it = 0; it < nk; ++it) {
        const int cur = it & 1;
        const bool more = (it + 1 < nk);
        if (more) {
            int off = (it + 1) * 16;
            ra0 = __ldg((const float4*)(pA0 + off));
            ra1 = __ldg((const float4*)(pA1 + off));
            rw0 = __ldg((const float4*)(pW0 + off));
            rw1 = __ldg((const float4*)(pW1 + off));
        }

        const unsigned* Asu = (const unsigned*)As[cur];
        const unsigned* Wsu = (const unsigned*)Ws[cur];
#pragma unroll
        for (int kk = 0; kk < 16; kk += 8) {
            unsigned a[4][4], b[4][2];
#pragma unroll
            for (int mt = 0; mt < 4; mt++) {
                int r = wm * 64 + mt * 16 + gid;
                a[mt][0] = Asu[(r)     * GPAD + kk + tg];
                a[mt][1] = Asu[(r + 8) * GPAD + kk + tg];
                a[mt][2] = Asu[(r)     * GPAD + kk + tg + 4];
                a[mt][3] = Asu[(r + 8) * GPAD + kk + tg + 4];
            }
#pragma unroll
            for (int nt = 0; nt < 4; nt++) {
                int c = wn * 32 + nt * 8 + gid;
                b[nt][0] = Wsu[c * GPAD + kk + tg];
                b[nt][1] = Wsu[c * GPAD + kk + tg + 4];
            }
#pragma unroll
            for (int mt = 0; mt < 4; mt++)
#pragma unroll
                for (int nt = 0; nt < 4; nt++) {
                    float* d = acc[mt * 4 + nt];
                    asm volatile(
                        "mma.sync.aligned.m16n8k8.row.col.f32.tf32.tf32.f32 "
                        "{%0,%1,%2,%3}, {%4,%5,%6,%7}, {%8,%9}, {%0,%1,%2,%3};"
                        : "+f"(d[0]), "+f"(d[1]), "+f"(d[2]), "+f"(d[3])
                        : "r"(a[mt][0]), "r"(a[mt][1]), "r"(a[mt][2]), "r"(a[mt][3]),
                          "r"(b[nt][0]), "r"(b[nt][1]));
                }
        }

        if (more) {
            const int nb = cur ^ 1;
            unsigned* ap0 = (unsigned*)&As[nb][row0 * GPAD + kq];
            ap0[0] = f2tf32(ra0.x); ap0[1] = f2tf32(ra0.y);
            ap0[2] = f2tf32(ra0.z); ap0[3] = f2tf32(ra0.w);
            unsigned* ap1 = (unsigned*)&As[nb][row1 * GPAD + kq];
            ap1[0] = f2tf32(ra1.x); ap1[1] = f2tf32(ra1.y);
            ap1[2] = f2tf32(ra1.z); ap1[3] = f2tf32(ra1.w);
            unsigned* wp0 = (unsigned*)&Ws[nb][row0 * GPAD + kq];
            wp0[0] = f2tf32(rw0.x); wp0[1] = f2tf32(rw0.y);
            wp0[2] = f2tf32(rw0.z); wp0[3] = f2tf32(rw0.w);
            unsigned* wp1 = (unsigned*)&Ws[nb][row1 * GPAD + kq];
            wp1[0] = f2tf32(rw1.x); wp1[1] = f2tf32(rw1.y);
            wp1[2] = f2tf32(rw1.z); wp1[3] = f2tf32(rw1.w);
        }
        __syncthreads();
    }

#pragma unroll
    for (int mt = 0; mt < 4; mt++) {
#pragma unroll
        for (int nt = 0; nt < 4; nt++) {
            int c = n0 + wn * 32 + nt * 8 + 2 * tg;
            float b0 = bias[c], b1 = bias[c + 1];
            int r0 = m0 + wm * 64 + mt * 16 + gid;
            float* d = acc[mt * 4 + nt];
            float2 v0 = {d[0] + b0, d[1] + b1};
            float2 v1 = {d[2] + b0, d[3] + b1};
            *(float2*)(g_gx + ((size_t)dir * MROWS + r0) * G3H + c) = v0;
            *(float2*)(g_gx + ((size_t)dir * MROWS + r0 + 8) * G3H + c) = v1;
        }
    }
}

// ---------------------------------------------------------------------------
// Persistent recurrence. 128 blocks = dir(2) x jtile(64); 512 threads =
// 16 warps = K-split (32 k each); lane = batch.
// Step layout:
//   all warps: flag-wait -> h LDG -> FMA -> STS red[t&1] -> __syncthreads
//   warps 0-7 only: fold red[t&1] -> epilogue -> ghd/y store ->
//                   bar.sync 1,256 -> tid0 st.release
//   warps 8-15: skip tail, run ahead into step t+1 (their next STS hits
//   red[(t+1)&1]; red parity makes the overlap race-free, see sync chain).
// ---------------------------------------------------------------------------
#define REDSTR 516
#define REDHALF (12 * REDSTR)

__global__ void __launch_bounds__(512, 1) gru_persist(
    const float* __restrict__ wh_f, const float* __restrict__ bh_f,
    const float* __restrict__ wh_b, const float* __restrict__ bh_b,
    float* __restrict__ y)
{
    extern __shared__ ull smu[];
    ull* ws   = smu;                   // 6144 ull
    ull* redb = smu + 6144;            // 2 * REDHALF ull

    const int blk = blockIdx.x;
    const int dir = blk >> 6;
    const int jt  = blk & 63;
    const float* wh = dir ? wh_b : wh_f;
    const float* bh = dir ? bh_b : bh_f;

    const int tid  = threadIdx.x;
    const int w    = tid >> 5;        // K-slice 0..15
    const int lane = tid & 31;        // batch
    const int kbase = w * 32;

    // one-time: pack weights as {w[j0,k], w[j1,k]} with k-pairs adjacent
    for (int i = tid; i < 6144; i += 512) {
        int g   = i >> 11;
        int kp  = (i >> 3) & 255;
        int jp  = (i >> 1) & 3;
        int par = i & 1;
        int k   = kp * 2 + par;
        int j0  = jt * 8 + jp * 2;
        ws[i] = pack2(wh[((size_t)g * HID + j0)     * HID + k],
                      wh[((size_t)g * HID + j0 + 1) * HID + k]);
    }

    __shared__ unsigned s_base;
    if (tid == 0) s_base = g_flag[dir][jt >> 2][jt & 3];
    __syncthreads();
    const unsigned base = s_base;

    // epilogue mapping (tid < 256): eb = tid>>3, jh = tid&7
    const int eb   = tid >> 3;
    const int jh   = tid & 7;
    const int jp_e = jh >> 1;
    const int jh_e = jh & 1;
    const int j_e  = jt * 8 + jh;
    const float bR = __ldg(bh + j_e);
    const float bZ = __ldg(bh + HID + j_e);
    const float bN = __ldg(bh + 2 * HID + j_e);

    float hprev = 0.f;                // register-carried h (j_e, eb)

    const unsigned* myflag = &g_flag[dir][w][lane & 3];
    unsigned* relflag = &g_flag[dir][jt >> 2][jt & 3];
    float* ghd = g_h + (size_t)dir * HID * BATCH;

    // gx prefetch for t = 0
    float gr = 0.f, gz = 0.f, gn = 0.f;
    if (tid < 256) {
        const int tt0 = dir ? (SEQ - 1) : 0;
        const float* gxp = g_gx +
            ((size_t)(dir * SEQ + tt0) * BATCH + eb) * G3H + j_e;
        gr = __ldg(gxp);
        gz = __ldg(gxp + HID);
        gn = __ldg(gxp + 2 * HID);
    }

    for (int t = 0; t < SEQ; ++t) {
        const int tt = dir ? (SEQ - 1 - t) : t;
        ull* red = redb + (t & 1) * REDHALF;

        float hreg[32];
        if (t == 0) {
#pragma unroll
            for (int kk = 0; kk < 32; ++kk) hreg[kk] = 0.f;
        } else {
            // wait for my 4 producer jtiles (all lanes acquire -> ordering)
            const unsigned tgt = base + (unsigned)t;
            while (true) {
                unsigned v = ld_acquire(myflag);
                if (__all_sync(0xffffffffu, v >= tgt)) break;
            }
#pragma unroll
            for (int kk = 0; kk < 32; ++kk)
                hreg[kk] = ldcg(ghd + (kbase + kk) * BATCH + lane);
        }

        ull acc[12];
#pragma unroll
        for (int q = 0; q < 12; ++q) acc[q] = 0;

#pragma unroll
        for (int kk = 0; kk < 16; ++kk) {
            const int kp = w * 16 + kk;
            ull h0 = dup2(hreg[2 * kk]);
            ull h1 = dup2(hreg[2 * kk + 1]);
#pragma unroll
            for (int g = 0; g < 3; ++g) {
                const ulonglong2* wk =
                    (const ulonglong2*)(ws + g * 2048 + kp * 8);
#pragma unroll
                for (int jp = 0; jp < 4; ++jp) {
                    ulonglong2 v = wk[jp];
                    fma2(acc[jp * 3 + g], h0, v.x);
                    fma2(acc[jp * 3 + g], h1, v.y);
                }
            }
        }

#pragma unroll
        for (int q = 0; q < 12; ++q)
            red[q * REDSTR + w * 32 + lane] = acc[q];
        __syncthreads();

        if (tid < 256) {
            ull sR = 0, sZ = 0, sN = 0;
#pragma unroll
            for (int wp = 0; wp < 16; ++wp) {
                const ull* rp = red + wp * 32 + eb;
                sR = add2(sR, rp[(jp_e * 3 + 0) * REDSTR]);
                sZ = add2(sZ, rp[(jp_e * 3 + 1) * REDSTR]);
                sN = add2(sN, rp[(jp_e * 3 + 2) * REDSTR]);
            }
            float sr = half2f(sR, jh_e);
            float sz = half2f(sZ, jh_e);
            float sn = half2f(sN, jh_e);

            float R = sigf(gr + sr + bR);
            float Z = sigf(gz + sz + bZ);
            float N = tanh_fast(gn + R * (sn + bN));
            float hn = (1.f - Z) * N + Z * hprev;
            hprev = hn;

            y[((size_t)eb * SEQ + tt) * (2 * HID) + dir * HID + j_e] = hn;
            ghd[j_e * BATCH + eb] = hn;

            // prefetch gx for t+1
            if (t != SEQ - 1) {
                const int tn = dir ? (SEQ - 2 - t) : (t + 1);
                const float* gxp = g_gx +
                    ((size_t)(dir * SEQ + tn) * BATCH + eb) * G3H + j_e;
                gr = __ldg(gxp);
                gz = __ldg(gxp + HID);
                gn = __ldg(gxp + 2 * HID);
            }

            if (t != SEQ - 1) {
                asm volatile("bar.sync 1, 256;" ::: "memory");
                if (tid == 0)
                    st_release(relflag, base + (unsigned)t + 1u);
            }
        }
        // warps 8-15 fall through directly into the next iteration
    }
}

// ---------------------------------------------------------------------------
__global__ void final_h(const float* __restrict__ y0,
                        const float* __restrict__ y1,
                        float* __restrict__ hf, float* __restrict__ hb)
{
    int i = blockIdx.x * blockDim.x + threadIdx.x;
    if (i >= 2 * BATCH * HID) return;
    int l = i >> 14;
    int b = (i >> 9) & 31;
    int h = i & 511;
    const float* yy = l ? y1 : y0;
    hf[i] = yy[((size_t)b * SEQ + (SEQ - 1)) * (2 * HID) + h];
    hb[i] = yy[((size_t)b * SEQ + 0) * (2 * HID) + HID + h];
}

// ---------------------------------------------------------------------------
extern "C" void kernel_launch(void* const* d_in, const int* in_sizes, int n_in,
                              void* d_out, int out_size)
{
    const float* x     = (const float*)d_in[0];
    const float* wx_f0 = (const float*)d_in[1];
    const float* bx_f0 = (const float*)d_in[2];
    const float* wh_f0 = (const float*)d_in[3];
    const float* bh_f0 = (const float*)d_in[4];
    const float* wx_b0 = (const float*)d_in[5];
    const float* bx_b0 = (const float*)d_in[6];
    const float* wh_b0 = (const float*)d_in[7];
    const float* bh_b0 = (const float*)d_in[8];
    const float* wx_f1 = (const float*)d_in[9];
    const float* bx_f1 = (const float*)d_in[10];
    const float* wh_f1 = (const float*)d_in[11];
    const float* bh_f1 = (const float*)d_in[12];
    const float* wx_b1 = (const float*)d_in[13];
    const float* bx_b1 = (const float*)d_in[14];
    const float* wh_b1 = (const float*)d_in[15];
    const float* bh_b1 = (const float*)d_in[16];

    float* out = (float*)d_out;
    float* y1  = out;
    float* hf  = out + (size_t)BATCH * SEQ * 2 * HID;
    float* hb  = hf + (size_t)2 * BATCH * HID;

    float* y0 = nullptr;
    cudaGetSymbolAddress((void**)&y0, g_y0);

    static int smem_set = 0;
    const int SMEM = (6144 + 2 * REDHALF) * 8;    // 148224 B
    if (!smem_set) {
        cudaFuncSetAttribute(gru_persist,
                             cudaFuncAttributeMaxDynamicSharedMemorySize, SMEM);
        smem_set = 1;
    }

    dim3 gg(MROWS / 128, G3H / 128, 2);

    gemm_gx<<<gg, 256>>>(x, 512, wx_f0, bx_f0, wx_b0, bx_b0);
    gru_persist<<<128, 512, SMEM>>>(wh_f0, bh_f0, wh_b0, bh_b0, y0);

    gemm_gx<<<gg, 256>>>(y0, 1024, wx_f1, bx_f1, wx_b1, bx_b1);
    gru_persist<<<128, 512, SMEM>>>(wh_f1, bh_f1, wh_b1, bh_b1, y1);

    final_h<<<(2 * BATCH * HID + 255) / 256, 256>>>(y0, y1, hf, hb);
}

// round 15
// speedup vs baseline: 1.5723x; 1.5723x over previous
#include <cuda_runtime.h>
#include <cuda_bf16.h>
#include <cstddef>

// ---------------------------------------------------------------------------
// BiGRU: B=32, S=512, I=512, H=512, L=2, bidirectional.
//   gx  = x @ wx^T + bx  (tf32 tensor-core GEMM, double-buffered smem)
//   recurrence: persistent kernel, f32x2 FFMA, per-jtile release flags.
//   R10 structure; release path shortened: flag fires right after ghd
//   stores (y-store + gx-prefetch moved after release; no threadfence).
// ---------------------------------------------------------------------------

#define BATCH 32
#define SEQ   512
#define HID   512
#define G3H   1536
#define MROWS (SEQ * BATCH)   // 16384

typedef unsigned long long ull;

__device__ float g_gx[(size_t)2 * MROWS * G3H];
__device__ float g_y0[(size_t)BATCH * SEQ * 2 * HID];
__device__ float g_h[(size_t)2 * HID * BATCH];      // [dir][k][b]
__device__ unsigned g_flag[2][16][32];              // [dir][group][slot]

__device__ __forceinline__ unsigned ld_acquire(const unsigned* p) {
    unsigned v;
    asm volatile("ld.acquire.gpu.u32 %0, [%1];" : "=r"(v) : "l"(p) : "memory");
    return v;
}
__device__ __forceinline__ void st_release(unsigned* p, unsigned v) {
    asm volatile("st.release.gpu.u32 [%0], %1;" :: "l"(p), "r"(v) : "memory");
}
__device__ __forceinline__ float ldcg(const float* p) {
    float v;
    asm volatile("ld.global.cg.f32 %0, [%1];" : "=f"(v) : "l"(p));
    return v;
}
__device__ __forceinline__ unsigned f2tf32(float x) {
    unsigned u;
    asm("cvt.rna.tf32.f32 %0, %1;" : "=r"(u) : "f"(x));
    return u;
}
__device__ __forceinline__ void fma2(ull& acc, ull a, ull b) {
    asm("fma.rn.f32x2 %0, %1, %2, %0;" : "+l"(acc) : "l"(a), "l"(b));
}
__device__ __forceinline__ ull add2(ull a, ull b) {
    ull d;
    asm("add.rn.f32x2 %0, %1, %2;" : "=l"(d) : "l"(a), "l"(b));
    return d;
}
__device__ __forceinline__ ull dup2(float x) {
    ull d;
    asm("mov.b64 %0, {%1, %1};" : "=l"(d) : "r"(__float_as_uint(x)));
    return d;
}
__device__ __forceinline__ ull pack2(float lo, float hi) {
    ull d;
    asm("mov.b64 %0, {%1, %2};" : "=l"(d)
        : "r"(__float_as_uint(lo)), "r"(__float_as_uint(hi)));
    return d;
}
__device__ __forceinline__ float half2f(ull v, int hi) {
    unsigned lo, hh;
    asm("mov.b64 {%0, %1}, %2;" : "=r"(lo), "=r"(hh) : "l"(v));
    return __uint_as_float(hi ? hh : lo);
}
__device__ __forceinline__ float sigf(float x) {
    return 1.f / (1.f + __expf(-x));
}
__device__ __forceinline__ float tanh_fast(float x) {
    float e = __expf(2.f * x);
    return 1.f - 2.f / (e + 1.f);
}

// ---------------------------------------------------------------------------
// tf32 GEMM, 2-stage smem double buffer (unchanged, proven).
// ---------------------------------------------------------------------------
#define GPAD 20

__global__ void __launch_bounds__(256) gemm_gx(
    const float* __restrict__ X, int in_dim,
    const float* __restrict__ Wf, const float* __restrict__ bf,
    const float* __restrict__ Wb, const float* __restrict__ bb)
{
    __shared__ float As[2][128 * GPAD];
    __shared__ float Ws[2][128 * GPAD];

    const int dir = blockIdx.z;
    const float* W    = dir ? Wb : Wf;
    const float* bias = dir ? bb : bf;
    const int m0 = blockIdx.x * 128;
    const int n0 = blockIdx.y * 128;
    const int tid  = threadIdx.x;
    const int warp = tid >> 5;
    const int lane = tid & 31;
    const int wm = warp >> 2;
    const int wn = warp & 3;
    const int gid = lane >> 2;
    const int tg  = lane & 3;

    const int row0 = tid >> 2;
    const int kq   = (tid & 3) << 2;
    const int row1 = row0 + 64;

    const int mA0 = m0 + row0, mA1 = m0 + row1;
    const float* pA0 = X + ((size_t)(mA0 & 31) * SEQ + (size_t)(mA0 >> 5)) * in_dim + kq;
    const float* pA1 = X + ((size_t)(mA1 & 31) * SEQ + (size_t)(mA1 >> 5)) * in_dim + kq;
    const float* pW0 = W + (size_t)(n0 + row0) * in_dim + kq;
    const float* pW1 = W + (size_t)(n0 + row1) * in_dim + kq;

    const int nk = in_dim >> 4;

    float acc[16][4];
#pragma unroll
    for (int i = 0; i < 16; i++)
#pragma unroll
        for (int c = 0; c < 4; c++) acc[i][c] = 0.f;

    float4 ra0 = __ldg((const float4*)pA0);
    float4 ra1 = __ldg((const float4*)pA1);
    float4 rw0 = __ldg((const float4*)pW0);
    float4 rw1 = __ldg((const float4*)pW1);

    {
        unsigned* ap0 = (unsigned*)&As[0][row0 * GPAD + kq];
        ap0[0] = f2tf32(ra0.x); ap0[1] = f2tf32(ra0.y);
        ap0[2] = f2tf32(ra0.z); ap0[3] = f2tf32(ra0.w);
        unsigned* ap1 = (unsigned*)&As[0][row1 * GPAD + kq];
        ap1[0] = f2tf32(ra1.x); ap1[1] = f2tf32(ra1.y);
        ap1[2] = f2tf32(ra1.z); ap1[3] = f2tf32(ra1.w);
        unsigned* wp0 = (unsigned*)&Ws[0][row0 * GPAD + kq];
        wp0[0] = f2tf32(rw0.x); wp0[1] = f2tf32(rw0.y);
        wp0[2] = f2tf32(rw0.z); wp0[3] = f2tf32(rw0.w);
        unsigned* wp1 = (unsigned*)&Ws[0][row1 * GPAD + kq];
        wp1[0] = f2tf32(rw1.x); wp1[1] = f2tf32(rw1.y);
        wp1[2] = f2tf32(rw1.z); wp1[3] = f2tf32(rw1.w);
    }
    __syncthreads();

    for (int it = 0; it < nk; ++it) {
        const int cur = it & 1;
        const bool more = (it + 1 < nk);
        if (more) {
            int off = (it + 1) * 16;
            ra0 = __ldg((const float4*)(pA0 + off));
            ra1 = __ldg((const float4*)(pA1 + off));
            rw0 = __ldg((const float4*)(pW0 + off));
            rw1 = __ldg((const float4*)(pW1 + off));
        }

        const unsigned* Asu = (const unsigned*)As[cur];
        const unsigned* Wsu = (const unsigned*)Ws[cur];
#pragma unroll
        for (int kk = 0; kk < 16; kk += 8) {
            unsigned a[4][4], b[4][2];
#pragma unroll
            for (int mt = 0; mt < 4; mt++) {
                int r = wm * 64 + mt * 16 + gid;
                a[mt][0] = Asu[(r)     * GPAD + kk + tg];
                a[mt][1] = Asu[(r + 8) * GPAD + kk + tg];
                a[mt][2] = Asu[(r)     * GPAD + kk + tg + 4];
                a[mt][3] = Asu[(r + 8) * GPAD + kk + tg + 4];
            }
#pragma unroll
            for (int nt = 0; nt < 4; nt++) {
                int c = wn * 32 + nt * 8 + gid;
                b[nt][0] = Wsu[c * GPAD + kk + tg];
                b[nt][1] = Wsu[c * GPAD + kk + tg + 4];
            }
#pragma unroll
            for (int mt = 0; mt < 4; mt++)
#pragma unroll
                for (int nt = 0; nt < 4; nt++) {
                    float* d = acc[mt * 4 + nt];
                    asm volatile(
                        "mma.sync.aligned.m16n8k8.row.col.f32.tf32.tf32.f32 "
                        "{%0,%1,%2,%3}, {%4,%5,%6,%7}, {%8,%9}, {%0,%1,%2,%3};"
                        : "+f"(d[0]), "+f"(d[1]), "+f"(d[2]), "+f"(d[3])
                        : "r"(a[mt][0]), "r"(a[mt][1]), "r"(a[mt][2]), "r"(a[mt][3]),
                          "r"(b[nt][0]), "r"(b[nt][1]));
                }
        }

        if (more) {
            const int nb = cur ^ 1;
            unsigned* ap0 = (unsigned*)&As[nb][row0 * GPAD + kq];
            ap0[0] = f2tf32(ra0.x); ap0[1] = f2tf32(ra0.y);
            ap0[2] = f2tf32(ra0.z); ap0[3] = f2tf32(ra0.w);
            unsigned* ap1 = (unsigned*)&As[nb][row1 * GPAD + kq];
            ap1[0] = f2tf32(ra1.x); ap1[1] = f2tf32(ra1.y);
            ap1[2] = f2tf32(ra1.z); ap1[3] = f2tf32(ra1.w);
            unsigned* wp0 = (unsigned*)&Ws[nb][row0 * GPAD + kq];
            wp0[0] = f2tf32(rw0.x); wp0[1] = f2tf32(rw0.y);
            wp0[2] = f2tf32(rw0.z); wp0[3] = f2tf32(rw0.w);
            unsigned* wp1 = (unsigned*)&Ws[nb][row1 * GPAD + kq];
            wp1[0] = f2tf32(rw1.x); wp1[1] = f2tf32(rw1.y);
            wp1[2] = f2tf32(rw1.z); wp1[3] = f2tf32(rw1.w);
        }
        __syncthreads();
    }

#pragma unroll
    for (int mt = 0; mt < 4; mt++) {
#pragma unroll
        for (int nt = 0; nt < 4; nt++) {
            int c = n0 + wn * 32 + nt * 8 + 2 * tg;
            float b0 = bias[c], b1 = bias[c + 1];
            int r0 = m0 + wm * 64 + mt * 16 + gid;
            float* d = acc[mt * 4 + nt];
            float2 v0 = {d[0] + b0, d[1] + b1};
            float2 v1 = {d[2] + b0, d[3] + b1};
            *(float2*)(g_gx + ((size_t)dir * MROWS + r0) * G3H + c) = v0;
            *(float2*)(g_gx + ((size_t)dir * MROWS + r0 + 8) * G3H + c) = v1;
        }
    }
}

// ---------------------------------------------------------------------------
// Persistent recurrence (R10 structure). 128 blocks = dir(2) x jtile(64);
// 512 threads = 16 warps = K-split (32 k each); lane = batch.
// Per step: flag-wait -> h LDG -> FMA -> STS red -> sync ->
//   (tid<256) fold -> epilogue -> ghd store -> sync -> tid0 st.release ->
//   (tid<256) gx prefetch + y store  [moved AFTER release: not consumed
//   by other blocks, so the flag fires earlier].
// ---------------------------------------------------------------------------
#define REDSTR 516

__global__ void __launch_bounds__(512, 1) gru_persist(
    const float* __restrict__ wh_f, const float* __restrict__ bh_f,
    const float* __restrict__ wh_b, const float* __restrict__ bh_b,
    float* __restrict__ y)
{
    extern __shared__ ull smu[];
    ull* ws  = smu;            // 6144 ull
    ull* red = smu + 6144;     // 12*516 ull

    const int blk = blockIdx.x;
    const int dir = blk >> 6;
    const int jt  = blk & 63;
    const float* wh = dir ? wh_b : wh_f;
    const float* bh = dir ? bh_b : bh_f;

    const int tid  = threadIdx.x;
    const int w    = tid >> 5;        // K-slice 0..15
    const int lane = tid & 31;        // batch
    const int kbase = w * 32;

    // one-time: pack weights as {w[j0,k], w[j1,k]} with k-pairs adjacent
    for (int i = tid; i < 6144; i += 512) {
        int g   = i >> 11;
        int kp  = (i >> 3) & 255;
        int jp  = (i >> 1) & 3;
        int par = i & 1;
        int k   = kp * 2 + par;
        int j0  = jt * 8 + jp * 2;
        ws[i] = pack2(wh[((size_t)g * HID + j0)     * HID + k],
                      wh[((size_t)g * HID + j0 + 1) * HID + k]);
    }

    __shared__ unsigned s_base;
    if (tid == 0) s_base = g_flag[dir][jt >> 2][jt & 3];
    __syncthreads();
    const unsigned base = s_base;

    // epilogue mapping (tid < 256): eb = tid>>3, jh = tid&7
    const int eb   = tid >> 3;
    const int jh   = tid & 7;
    const int jp_e = jh >> 1;
    const int jh_e = jh & 1;
    const int j_e  = jt * 8 + jh;
    const float bR = __ldg(bh + j_e);
    const float bZ = __ldg(bh + HID + j_e);
    const float bN = __ldg(bh + 2 * HID + j_e);

    float hprev = 0.f;                // register-carried h (j_e, eb)

    const unsigned* myflag = &g_flag[dir][w][lane & 3];
    unsigned* relflag = &g_flag[dir][jt >> 2][jt & 3];
    float* ghd = g_h + (size_t)dir * HID * BATCH;

    // gx prefetch for t = 0
    float gr = 0.f, gz = 0.f, gn = 0.f;
    if (tid < 256) {
        const int tt0 = dir ? (SEQ - 1) : 0;
        const float* gxp = g_gx +
            ((size_t)(dir * SEQ + tt0) * BATCH + eb) * G3H + j_e;
        gr = __ldg(gxp);
        gz = __ldg(gxp + HID);
        gn = __ldg(gxp + 2 * HID);
    }

    for (int t = 0; t < SEQ; ++t) {
        const int tt = dir ? (SEQ - 1 - t) : t;

        // h slice straight into registers (coalesced LDG from L2)
        float hreg[32];
        if (t == 0) {
#pragma unroll
            for (int kk = 0; kk < 32; ++kk) hreg[kk] = 0.f;
        } else {
            // wait for my 4 producer jtiles (all lanes acquire -> ordering)
            const unsigned tgt = base + (unsigned)t;
            while (true) {
                unsigned v = ld_acquire(myflag);
                if (__all_sync(0xffffffffu, v >= tgt)) break;
            }
#pragma unroll
            for (int kk = 0; kk < 32; ++kk)
                hreg[kk] = ldcg(ghd + (kbase + kk) * BATCH + lane);
        }

        ull acc[12];
#pragma unroll
        for (int q = 0; q < 12; ++q) acc[q] = 0;

#pragma unroll
        for (int kk = 0; kk < 16; ++kk) {
            const int kp = w * 16 + kk;
            ull h0 = dup2(hreg[2 * kk]);
            ull h1 = dup2(hreg[2 * kk + 1]);
#pragma unroll
            for (int g = 0; g < 3; ++g) {
                const ulonglong2* wk =
                    (const ulonglong2*)(ws + g * 2048 + kp * 8);
#pragma unroll
                for (int jp = 0; jp < 4; ++jp) {
                    ulonglong2 v = wk[jp];
                    fma2(acc[jp * 3 + g], h0, v.x);
                    fma2(acc[jp * 3 + g], h1, v.y);
                }
            }
        }

#pragma unroll
        for (int q = 0; q < 12; ++q)
            red[q * REDSTR + w * 32 + lane] = acc[q];
        __syncthreads();

        float hn = 0.f;
        if (tid < 256) {
            ull sR = 0, sZ = 0, sN = 0;
#pragma unroll
            for (int wp = 0; wp < 16; ++wp) {
                const ull* rp = red + wp * 32 + eb;
                sR = add2(sR, rp[(jp_e * 3 + 0) * REDSTR]);
                sZ = add2(sZ, rp[(jp_e * 3 + 1) * REDSTR]);
                sN = add2(sN, rp[(jp_e * 3 + 2) * REDSTR]);
            }
            float sr = half2f(sR, jh_e);
            float sz = half2f(sZ, jh_e);
            float sn = half2f(sN, jh_e);

            float R = sigf(gr + sr + bR);
            float Z = sigf(gz + sz + bZ);
            float N = tanh_fast(gn + R * (sn + bN));
            hn = (1.f - Z) * N + Z * hprev;
            hprev = hn;

            ghd[j_e * BATCH + eb] = hn;      // the only cross-block payload
        }

        if (t != SEQ - 1) {
            __syncthreads();                 // ghd stores complete block-wide
            if (tid == 0)
                st_release(relflag, base + (unsigned)t + 1u);
        }

        if (tid < 256) {
            // post-release work: gx prefetch for t+1, then y store
            if (t != SEQ - 1) {
                const int tn = dir ? (SEQ - 2 - t) : (t + 1);
                const float* gxp = g_gx +
                    ((size_t)(dir * SEQ + tn) * BATCH + eb) * G3H + j_e;
                gr = __ldg(gxp);
                gz = __ldg(gxp + HID);
                gn = __ldg(gxp + 2 * HID);
            }
            y[((size_t)eb * SEQ + tt) * (2 * HID) + dir * HID + j_e] = hn;
        }
    }
}

// ---------------------------------------------------------------------------
__global__ void final_h(const float* __restrict__ y0,
                        const float* __restrict__ y1,
                        float* __restrict__ hf, float* __restrict__ hb)
{
    int i = blockIdx.x * blockDim.x + threadIdx.x;
    if (i >= 2 * BATCH * HID) return;
    int l = i >> 14;
    int b = (i >> 9) & 31;
    int h = i & 511;
    const float* yy = l ? y1 : y0;
    hf[i] = yy[((size_t)b * SEQ + (SEQ - 1)) * (2 * HID) + h];
    hb[i] = yy[((size_t)b * SEQ + 0) * (2 * HID) + HID + h];
}

// ---------------------------------------------------------------------------
extern "C" void kernel_launch(void* const* d_in, const int* in_sizes, int n_in,
                              void* d_out, int out_size)
{
    const float* x     = (const float*)d_in[0];
    const float* wx_f0 = (const float*)d_in[1];
    const float* bx_f0 = (const float*)d_in[2];
    const float* wh_f0 = (const float*)d_in[3];
    const float* bh_f0 = (const float*)d_in[4];
    const float* wx_b0 = (const float*)d_in[5];
    const float* bx_b0 = (const float*)d_in[6];
    const float* wh_b0 = (const float*)d_in[7];
    const float* bh_b0 = (const float*)d_in[8];
    const float* wx_f1 = (const float*)d_in[9];
    const float* bx_f1 = (const float*)d_in[10];
    const float* wh_f1 = (const float*)d_in[11];
    const float* bh_f1 = (const float*)d_in[12];
    const float* wx_b1 = (const float*)d_in[13];
    const float* bx_b1 = (const float*)d_in[14];
    const float* wh_b1 = (const float*)d_in[15];
    const float* bh_b1 = (const float*)d_in[16];

    float* out = (float*)d_out;
    float* y1  = out;
    float* hf  = out + (size_t)BATCH * SEQ * 2 * HID;
    float* hb  = hf + (size_t)2 * BATCH * HID;

    float* y0 = nullptr;
    cudaGetSymbolAddress((void**)&y0, g_y0);

    static int smem_set = 0;
    const int SMEM = (6144 + 12 * REDSTR) * 8;    // 98688 B
    if (!smem_set) {
        cudaFuncSetAttribute(gru_persist,
                             cudaFuncAttributeMaxDynamicSharedMemorySize, SMEM);
        smem_set = 1;
    }

    dim3 gg(MROWS / 128, G3H / 128, 2);

    gemm_gx<<<gg, 256>>>(x, 512, wx_f0, bx_f0, wx_b0, bx_b0);
    gru_persist<<<128, 512, SMEM>>>(wh_f0, bh_f0, wh_b0, bh_b0, y0);

    gemm_gx<<<gg, 256>>>(y0, 1024, wx_f1, bx_f1, wx_b1, bx_b1);
    gru_persist<<<128, 512, SMEM>>>(wh_f1, bh_f1, wh_b1, bh_b1, y1);

    final_h<<<(2 * BATCH * HID + 255) / 256, 256>>>(y0, y1, hf, hb);
}